// round 11
// baseline (speedup 1.0000x reference)
#include <cuda_runtime.h>
#include <cuda_bf16.h>

// RGBToHVI: elementwise, planar (16, 3, 1024, 1024) fp32. HBM-bound (~402 MB).
// V4b: persistent grid-stride (1216 CTAs = 152 SM x 8) over the V3 body.
// (R10 was an infra failure — re-bench of the same design, with the loop
// induction variable kept in float4-index space to drop one IMAD/iter.)
// Removes ~13 wave transitions + per-CTA setup; <=36 regs via
// launch_bounds(256,7). Branchless hue cascade, streaming cache hints.

#define PLANE4   262144            // (1024*1024)/4 float4 per channel plane
#define NPIX4    4194304           // 16 * PLANE4
#define EPS_F    1e-8f
#define PI_F     3.14159265358979f

__device__ __forceinline__ void hvi_pixel(float r, float g, float b, float k,
                                          float& X, float& Y, float& Z)
{
    const float v  = fmaxf(r, fmaxf(g, b));
    const float mn = fminf(r, fminf(g, b));
    const float chroma = v - mn;
    const float rd = __frcp_rn(chroma + EPS_F);

    // Branchless jnp.where cascade (later where wins):
    //   priority: mn==v -> 0, r==v -> mod6 arm, g==v, b==v, else 0
    float hr = (g - b) * rd;                      // in [-1, 1]
    hr = (hr < 0.0f) ? hr + 6.0f : hr;            // x % 6.0 (positive divisor)
    const float hg = 2.0f + (b - r) * rd;
    const float hb = 4.0f + (r - g) * rd;

    float hue = (b == v)  ? hb   : 0.0f;
    hue       = (g == v)  ? hg   : hue;
    hue       = (r == v)  ? hr   : hue;
    hue       = (mn == v) ? 0.0f : hue;
    hue *= (1.0f / 6.0f);

    const float sat = (v == 0.0f) ? 0.0f : chroma * __frcp_rn(v + EPS_F);

    // color_sensitive = (sin(v*pi/2) + eps)^k, v in [0,1] so base >= eps > 0
    const float s  = __sinf(v * (0.5f * PI_F)) + EPS_F;
    const float cs = __powf(s, k);                // EX2(k * LG2(s))

    const float ang = (2.0f * PI_F) * hue;
    const float m = cs * sat;
    X = m * __cosf(ang);
    Y = m * __sinf(ang);
    Z = v;
}

__global__ __launch_bounds__(256, 7)
void rgb_to_hvi_kernel(const float4* __restrict__ img,
                       const float*  __restrict__ dk,
                       float4* __restrict__ out)
{
    const float k = __ldg(dk);

    const int step  = gridDim.x * 256;            // float4 elems per grid pass
    const int start = blockIdx.x * 256 + threadIdx.x;

    for (int i = start; i < NPIX4; i += step) {
        const int batch = i >> 18;                // / PLANE4
        const int w     = i & (PLANE4 - 1);
        const long base = (long)batch * (3 * PLANE4) + w;

        // Three front-batched 128-bit streaming loads
        const float4 rv = __ldcs(&img[base]);
        const float4 gv = __ldcs(&img[base + PLANE4]);
        const float4 bv = __ldcs(&img[base + 2 * PLANE4]);

        float4 Xv, Yv, Zv;
        hvi_pixel(rv.x, gv.x, bv.x, k, Xv.x, Yv.x, Zv.x);
        hvi_pixel(rv.y, gv.y, bv.y, k, Xv.y, Yv.y, Zv.y);
        hvi_pixel(rv.z, gv.z, bv.z, k, Xv.z, Yv.z, Zv.z);
        hvi_pixel(rv.w, gv.w, bv.w, k, Xv.w, Yv.w, Zv.w);

        __stcs(&out[base],              Xv);
        __stcs(&out[base + PLANE4],     Yv);
        __stcs(&out[base + 2 * PLANE4], Zv);
    }
}

extern "C" void kernel_launch(void* const* d_in, const int* in_sizes, int n_in,
                              void* d_out, int out_size)
{
    const float4* img = (const float4*)d_in[0];
    const float*  dk  = (const float*)d_in[1];
    float4* out = (float4*)d_out;

    const int threads = 256;
    const int blocks  = 152 * 8;                  // persistent: GB300 has 152 SMs
    rgb_to_hvi_kernel<<<blocks, threads>>>(img, dk, out);
}

// round 15
// speedup vs baseline: 1.1789x; 1.1789x over previous
#include <cuda_runtime.h>
#include <cuda_bf16.h>

// RGBToHVI: elementwise, planar (16, 3, 1024, 1024) fp32. HBM-bound (~402 MB).
// V5: best-of-measured recombination. One-shot 16384-CTA grid (CTA churn acts
// as prefetch — persistent V4 lost 7pts DRAM), branchless hue cascade (V3),
// default cache policy (V1 beat .cs variants on DRAM%), Z stored first.
// 32 regs, occ ~86%.

#define PLANE4   262144            // (1024*1024)/4 float4 per channel plane
#define NPIX4    4194304           // 16 * PLANE4
#define EPS_F    1e-8f
#define PI_F     3.14159265358979f

__device__ __forceinline__ void hvi_pixel(float r, float g, float b, float k,
                                          float& X, float& Y, float& Z)
{
    const float v  = fmaxf(r, fmaxf(g, b));
    const float mn = fminf(r, fminf(g, b));
    const float chroma = v - mn;
    const float rd = __frcp_rn(chroma + EPS_F);

    // Branchless jnp.where cascade (later where wins):
    //   priority: mn==v -> 0, r==v -> mod6 arm, g==v, b==v, else 0
    float hr = (g - b) * rd;                      // in [-1, 1]
    hr = (hr < 0.0f) ? hr + 6.0f : hr;            // x % 6.0 (positive divisor)
    const float hg = 2.0f + (b - r) * rd;
    const float hb = 4.0f + (r - g) * rd;

    float hue = (b == v)  ? hb   : 0.0f;
    hue       = (g == v)  ? hg   : hue;
    hue       = (r == v)  ? hr   : hue;
    hue       = (mn == v) ? 0.0f : hue;
    hue *= (1.0f / 6.0f);

    const float sat = (v == 0.0f) ? 0.0f : chroma * __frcp_rn(v + EPS_F);

    // color_sensitive = (sin(v*pi/2) + eps)^k, v in [0,1] so base >= eps > 0
    const float s  = __sinf(v * (0.5f * PI_F)) + EPS_F;
    const float cs = __powf(s, k);                // EX2(k * LG2(s))

    const float ang = (2.0f * PI_F) * hue;
    const float m = cs * sat;
    X = m * __cosf(ang);
    Y = m * __sinf(ang);
    Z = v;
}

__global__ __launch_bounds__(256, 8)
void rgb_to_hvi_kernel(const float4* __restrict__ img,
                       const float*  __restrict__ dk,
                       float4* __restrict__ out)
{
    const int i = blockIdx.x * blockDim.x + threadIdx.x;

    const float k = __ldg(dk);

    const int batch = i >> 18;                    // / PLANE4
    const int w     = i & (PLANE4 - 1);
    const long base = (long)batch * (3 * PLANE4) + w;

    // Three front-batched 128-bit loads (default cache policy — measured best)
    const float4 rv = img[base];
    const float4 gv = img[base + PLANE4];
    const float4 bv = img[base + 2 * PLANE4];

    float4 Xv, Yv, Zv;
    hvi_pixel(rv.x, gv.x, bv.x, k, Xv.x, Yv.x, Zv.x);
    hvi_pixel(rv.y, gv.y, bv.y, k, Xv.y, Yv.y, Zv.y);
    hvi_pixel(rv.z, gv.z, bv.z, k, Xv.z, Yv.z, Zv.z);
    hvi_pixel(rv.w, gv.w, bv.w, k, Xv.w, Yv.w, Zv.w);

    // Z (=value) is ready earliest — store it first to retire regs sooner.
    out[base + 2 * PLANE4] = Zv;
    out[base]              = Xv;
    out[base + PLANE4]     = Yv;
}

extern "C" void kernel_launch(void* const* d_in, const int* in_sizes, int n_in,
                              void* d_out, int out_size)
{
    const float4* img = (const float4*)d_in[0];
    const float*  dk  = (const float*)d_in[1];
    float4* out = (float4*)d_out;

    const int threads = 256;
    const int blocks  = NPIX4 / threads;          // 16384 (exact)
    rgb_to_hvi_kernel<<<blocks, threads>>>(img, dk, out);
}